// round 2
// baseline (speedup 1.0000x reference)
#include <cuda_runtime.h>
#include <math.h>

// Problem constants
#define TT   4096
#define BB   32
#define HH   512
#define HB   (HH * BB)          // 16384 floats per step
#define NCTA 128                // persistent CTAs (<= 148 SMs -> all wave-1 resident)
#define UNITS 4                 // hidden units per CTA (512 / 128)
#define ROWS  16                // gate rows per CTA (4 gates x 4 units)
#define NTHR  256

// Inter-step hidden state, laid out [t][j][b] (b fastest -> coalesced per-j rows).
// Distinct buffer per step => one-way producer/consumer sync, no anti-dependency.
__device__ float        g_h[(size_t)TT * HB];   // ~268 MB static scratch
__device__ unsigned int g_ctr[TT];              // per-step completion counters

// Re-initializes per-replay state: y = x0 + b_lin (d_out is poisoned to 0xAA),
// and zeroes the step counters. Runs before the persistent kernel each launch.
__global__ void init_kernel(const float* __restrict__ x0,
                            const float* __restrict__ b_lin,
                            float* __restrict__ y, int n)
{
    int i = blockIdx.x * blockDim.x + threadIdx.x;
    if (i < n)  y[i] = x0[i] + b_lin[0];
    if (i < TT) g_ctr[i] = 0u;
}

__global__ void __launch_bounds__(NTHR, 1)
lstm_kernel(const float* __restrict__ x0,     // (T,B,1)
            const float* __restrict__ W_ih,   // (4H,1)
            const float* __restrict__ W_hh,   // (4H,H) row-major
            const float* __restrict__ b_ih,   // (4H)
            const float* __restrict__ b_hh,   // (4H)
            const float* __restrict__ W_lin,  // (1,H)
            float* __restrict__ y)            // (T,B,1)
{
    // k-major W slice: W_s[k][r], r = gate*4 + unit. 16 floats (64B) per k ->
    // one broadcast LDS.128 fetches 4 rows (one gate, all 4 units) per k.
    __shared__ __align__(16) float W_s[HH * ROWS];   // 32 KB
    __shared__ float part[NTHR * 4];                 // per-warp dot partials
    __shared__ float x0_s[BB];
    __shared__ float wih_s[ROWS], bsum_s[ROWS], wlin_s[UNITS];
    __shared__ float ysum[128];

    const int tid  = threadIdx.x;
    const int lane = tid & 31;                 // lane == batch index
    const int w    = tid >> 5;                 // warp 0..7
    const int cta  = blockIdx.x;
    const int j0   = cta * UNITS;              // first hidden unit owned

    // Stage W_hh slice (transposed to k-major), W_ih + fused bias, W_lin slice.
    for (int idx = tid; idx < ROWS * HH; idx += NTHR) {
        int r = idx >> 9;                      // local row 0..15
        int k = idx & (HH - 1);
        int grow = (r >> 2) * HH + j0 + (r & 3);   // gate*512 + j0 + unit
        W_s[k * ROWS + r] = W_hh[(size_t)grow * HH + k];
    }
    if (tid < ROWS) {
        int grow = (tid >> 2) * HH + j0 + (tid & 3);
        wih_s[tid]  = W_ih[grow];
        bsum_s[tid] = b_ih[grow] + b_hh[grow];
    }
    if (tid < UNITS) wlin_s[tid] = W_lin[j0 + tid];
    __syncthreads();

    // Warp work split: gate = w&3 (one gate x 4 units), k-half = w>>2.
    const int gate = w & 3;
    const int kbeg = (w >> 2) * (HH / 2);

    // Epilogue threads (tid<128): thread (u, b) owns cell state c[j0+u][b].
    const int u_ep = tid >> 5;
    float c_reg = 0.0f;

    for (int t = 0; t < TT; ++t) {
        // ---- wait for h[t-1] from all CTAs (one-way flag) ----
        if (t > 0 && tid == 0) {
            while (atomicAdd(&g_ctr[t - 1], 0u) < (unsigned)NCTA) { }
        }
        if (tid < BB) x0_s[tid] = x0[t * BB + tid];
        __syncthreads();

        // ---- gate dot products: acc[u] = sum_k W[gate,u][k] * h[t-1][k][b] ----
        float a0 = 0.f, a1 = 0.f, a2 = 0.f, a3 = 0.f;
        if (t > 0) {
            const float* hrow = g_h + (size_t)(t - 1) * HB;
            #pragma unroll 8
            for (int k = kbeg; k < kbeg + HH / 2; ++k) {
                float  hv = hrow[k * BB + lane];                 // coalesced 128B
                float4 wv = *reinterpret_cast<const float4*>(
                                &W_s[k * ROWS + gate * 4]);      // broadcast LDS.128
                a0 = fmaf(wv.x, hv, a0);
                a1 = fmaf(wv.y, hv, a1);
                a2 = fmaf(wv.z, hv, a2);
                a3 = fmaf(wv.w, hv, a3);
            }
        }
        {
            int pb = (w * 4) * 32 + lane;      // [(half*4+gate)*4 + u][b]
            part[pb]      = a0;
            part[pb + 32] = a1;
            part[pb + 64] = a2;
            part[pb + 96] = a3;
        }
        __syncthreads();

        // ---- LSTM cell epilogue: 128 threads = 4 units x 32 batches ----
        if (tid < 128) {
            const int   b  = lane;
            const float xv = x0_s[b];
            float gs[4];
            #pragma unroll
            for (int G = 0; G < 4; ++G) {
                int r = G * 4 + u_ep;
                gs[G] = part[r * 32 + b] + part[(16 + r) * 32 + b]
                      + fmaf(wih_s[r], xv, bsum_s[r]);
            }
            float ig = 1.0f / (1.0f + __expf(-gs[0]));
            float fg = 1.0f / (1.0f + __expf(-gs[1]));
            float gg = tanhf(gs[2]);
            float og = 1.0f / (1.0f + __expf(-gs[3]));
            c_reg = fmaf(fg, c_reg, ig * gg);
            float hv = og * tanhf(c_reg);

            g_h[(size_t)t * HB + (j0 + u_ep) * BB + b] = hv;
            ysum[u_ep * 32 + b] = hv * wlin_s[u_ep];
            __threadfence();                   // publish h writes to L2 (gpu scope)
        }
        __syncthreads();

        // ---- partial y contribution + completion flag ----
        if (tid < BB) {
            float yp = ysum[tid] + ysum[32 + tid] + ysum[64 + tid] + ysum[96 + tid];
            atomicAdd(&y[t * BB + tid], yp);
        }
        if (tid == 0) atomicAdd(&g_ctr[t], 1u);
    }
}

extern "C" void kernel_launch(void* const* d_in, const int* in_sizes, int n_in,
                              void* d_out, int out_size)
{
    const float* x0    = (const float*)d_in[0];
    const float* W_ih  = (const float*)d_in[1];
    const float* W_hh  = (const float*)d_in[2];
    const float* b_ih  = (const float*)d_in[3];
    const float* b_hh  = (const float*)d_in[4];
    const float* W_lin = (const float*)d_in[5];
    const float* b_lin = (const float*)d_in[6];
    float* y = (float*)d_out;

    const int n = TT * BB;
    init_kernel<<<(n + NTHR - 1) / NTHR, NTHR>>>(x0, b_lin, y, n);
    lstm_kernel<<<NCTA, NTHR>>>(x0, W_ih, W_hh, b_ih, b_hh, W_lin, y);
}

// round 3
// speedup vs baseline: 2.0765x; 2.0765x over previous
#include <cuda_runtime.h>

// Problem constants
#define TT    4096
#define BB    32
#define HH    512
#define HB    (HH * BB)            // 16384 floats per step
#define NCTA  128                  // persistent CTAs, all wave-1 resident
#define UNITS 4                    // hidden units per CTA
#define ROWS  16                   // gate rows per CTA (4 gates x 4 units)
#define NTHR  512                  // 16 warps
#define NSEG  8                    // k-segments per row dot product

// Dynamic SMEM layout (floats)
#define SMEM_W2   (HH * ROWS * 2)  // duplicated weight pairs: 16384 floats = 64KB
#define SMEM_PART (ROWS * NSEG * BB) // 4096 floats = 16KB
#define SMEM_FLOATS (SMEM_W2 + SMEM_PART + 64)
#define SMEM_BYTES (SMEM_FLOATS * 4)

// Inter-step hidden state [t][j][b] (b fastest). Distinct buffer per step
// => one-way producer/consumer sync, no anti-dependency.
__device__ float    g_h[(size_t)TT * HB];   // ~268 MB static scratch
__device__ unsigned g_ctr[TT];              // per-step completion counters

__global__ void init_kernel() {
    int i = blockIdx.x * blockDim.x + threadIdx.x;
    if (i < TT) g_ctr[i] = 0u;
}

// Packed f32x2 FMA (Blackwell packed fp32 pipe; ptxas never auto-fuses this).
__device__ __forceinline__ void fma2(unsigned long long& d,
                                     unsigned long long a,
                                     unsigned long long b) {
    asm("fma.rn.f32x2 %0, %1, %2, %0;" : "+l"(d) : "l"(a), "l"(b));
}

// Fast-but-accurate activations (~1e-7 abs err; tanh.approx's 2^-11 is too
// risky through a 4096-step recurrence against the 1e-3 gate).
__device__ __forceinline__ float sig_f(float x) {
    return __fdividef(1.0f, 1.0f + __expf(-x));
}
__device__ __forceinline__ float tanh_f(float x) {
    return fmaf(-2.0f, __fdividef(1.0f, 1.0f + __expf(2.0f * x)), 1.0f);
}

__global__ void __launch_bounds__(NTHR, 1)
lstm_kernel(const float* __restrict__ x0,     // (T,B,1)
            const float* __restrict__ W_ih,   // (4H,1)
            const float* __restrict__ W_hh,   // (4H,H) row-major
            const float* __restrict__ b_ih,   // (4H)
            const float* __restrict__ b_hh)   // (4H)
{
    extern __shared__ float sm[];
    float* W2   = sm;                    // [k][r] duplicated pairs (w,w)
    float* part = sm + SMEM_W2;          // [r][seg][b]
    float* x0s  = part + SMEM_PART;      // 32
    float* wih  = x0s + 32;              // 16
    float* bsum = wih + 16;              // 16

    const int tid  = threadIdx.x;
    const int lane = tid & 31;
    const int w    = tid >> 5;           // warp 0..15
    const int gate = w & 3;              // this warp's gate
    const int kq   = w >> 2;             // k-quarter 0..3
    const int kh   = lane >> 4;          // k-half within quarter
    const int p    = lane & 15;          // batch pair 0..15 -> batches 2p,2p+1
    const int seg  = kq * 2 + kh;        // 0..7
    const int kbeg = kq * 128 + kh * 64; // 64 k-iters per lane
    const int j0   = blockIdx.x * UNITS;

    // Stage W_hh slice, transposed to k-major, each weight duplicated so the
    // inner loop needs zero packing MOVs. SMEM writes conflict-free (r fastest).
    for (int idx = tid; idx < ROWS * HH; idx += NTHR) {
        int r = idx & 15, k = idx >> 4;
        int grow = (r >> 2) * HH + j0 + (r & 3);   // gate*512 + j0 + unit
        float wv = W_hh[(size_t)grow * HH + k];
        W2[(k * ROWS + r) * 2 + 0] = wv;
        W2[(k * ROWS + r) * 2 + 1] = wv;
    }
    if (tid < ROWS) {
        int grow = (tid >> 2) * HH + j0 + (tid & 3);
        wih[tid]  = W_ih[grow];
        bsum[tid] = b_ih[grow] + b_hh[grow];
    }
    __syncthreads();

    // Epilogue threads (tid<128): thread (u, b) owns cell state c[j0+u][b].
    float c_reg = 0.0f;

    for (int t = 0; t < TT; ++t) {
        if (tid < BB) x0s[tid] = x0[t * BB + tid];
        // One-way flag wait: plain L2 loads (no atomic-ALU serialization),
        // single acquire fence per CTA per step.
        if (t && tid == 0) {
            unsigned v;
            do {
                asm volatile("ld.global.cg.u32 %0, [%1];"
                             : "=r"(v) : "l"(g_ctr + (t - 1)) : "memory");
            } while (v < (unsigned)NCTA);
            __threadfence();   // acquire side (cumulative via barrier below)
        }
        __syncthreads();

        // ---- gate dots: acc[u] = sum_k W[gate,u][k] * h[t-1][k][2p..2p+1] ----
        unsigned long long a0 = 0, a1 = 0, a2 = 0, a3 = 0;
        if (t) {
            const char* hbase = (const char*)(g_h + (size_t)(t - 1) * HB + 2 * p);
            const char* wbase = (const char*)(W2 + gate * 8);
            #pragma unroll 8
            for (int k = kbeg; k < kbeg + 64; ++k) {
                unsigned long long hp =
                    *(const unsigned long long*)(hbase + (size_t)k * 128); // LDG.64
                ulonglong2 wa = *(const ulonglong2*)(wbase + k * 128);      // LDS.128
                ulonglong2 wb = *(const ulonglong2*)(wbase + k * 128 + 16); // LDS.128
                fma2(a0, wa.x, hp);
                fma2(a1, wa.y, hp);
                fma2(a2, wb.x, hp);
                fma2(a3, wb.y, hp);
            }
        }
        {
            float* pb = part + seg * 32 + 2 * p;
            *(unsigned long long*)(pb + (gate * 4 + 0) * 256) = a0;
            *(unsigned long long*)(pb + (gate * 4 + 1) * 256) = a1;
            *(unsigned long long*)(pb + (gate * 4 + 2) * 256) = a2;
            *(unsigned long long*)(pb + (gate * 4 + 3) * 256) = a3;
        }
        __syncthreads();

        // ---- LSTM cell epilogue: 128 threads = 4 units x 32 batches ----
        if (tid < 128) {
            const int u = tid >> 5, b = tid & 31;
            const float xv = x0s[b];
            float gs[4];
            #pragma unroll
            for (int G = 0; G < 4; ++G) {
                const int r = G * 4 + u;
                const float* pr = part + r * 256 + b;
                float s = 0.0f;
                #pragma unroll
                for (int ss = 0; ss < NSEG; ++ss) s += pr[ss * 32];
                gs[G] = s + fmaf(wih[r], xv, bsum[r]);
            }
            float ig = sig_f(gs[0]);
            float fg = sig_f(gs[1]);
            float gg = tanh_f(gs[2]);
            float og = sig_f(gs[3]);
            c_reg = fmaf(fg, c_reg, ig * gg);
            float hv = og * tanh_f(c_reg);
            g_h[(size_t)t * HB + (j0 + u) * BB + b] = hv;
        }
        __syncthreads();

        // Single release fence + single RED per CTA per step.
        if (tid == 0) {
            __threadfence();
            atomicAdd(&g_ctr[t], 1u);   // return unused -> RED
        }
    }
}

// y[t][b] = x0 + b_lin + sum_j W_lin[j] * h[t][j][b]  — fully parallel over t,
// hoisted off the recurrence critical path. DRAM-bound: ~268MB read ≈ 40us.
__global__ void __launch_bounds__(256)
y_kernel(const float* __restrict__ x0,
         const float* __restrict__ W_lin,
         const float* __restrict__ b_lin,
         float* __restrict__ y)
{
    __shared__ float wl_s[HH];
    __shared__ float red[256];
    const int t = blockIdx.x, tid = threadIdx.x;
    for (int i = tid; i < HH; i += 256) wl_s[i] = W_lin[i];
    __syncthreads();
    const int b = tid & 31, jg = tid >> 5;
    const float* h = g_h + (size_t)t * HB;
    float acc = 0.0f;
    #pragma unroll 4
    for (int j = jg * 64; j < jg * 64 + 64; ++j)
        acc = fmaf(h[j * 32 + b], wl_s[j], acc);
    red[tid] = acc;
    __syncthreads();
    if (tid < 32) {
        float s = 0.0f;
        #pragma unroll
        for (int g = 0; g < 8; ++g) s += red[g * 32 + tid];
        y[t * BB + tid] = s + x0[t * BB + tid] + b_lin[0];
    }
}

extern "C" void kernel_launch(void* const* d_in, const int* in_sizes, int n_in,
                              void* d_out, int out_size)
{
    const float* x0    = (const float*)d_in[0];
    const float* W_ih  = (const float*)d_in[1];
    const float* W_hh  = (const float*)d_in[2];
    const float* b_ih  = (const float*)d_in[3];
    const float* b_hh  = (const float*)d_in[4];
    const float* W_lin = (const float*)d_in[5];
    const float* b_lin = (const float*)d_in[6];
    float* y = (float*)d_out;

    cudaFuncSetAttribute(lstm_kernel,
                         cudaFuncAttributeMaxDynamicSharedMemorySize, SMEM_BYTES);

    init_kernel<<<(TT + 255) / 256, 256>>>();
    lstm_kernel<<<NCTA, NTHR, SMEM_BYTES>>>(x0, W_ih, W_hh, b_ih, b_hh);
    y_kernel<<<TT, 256>>>(x0, W_lin, b_lin, y);
}

// round 4
// speedup vs baseline: 2.1532x; 1.0369x over previous
#include <cuda_runtime.h>
#include <math.h>

// Problem constants
#define TT    4096
#define BB    32
#define HH    512
#define HB    (HH * BB)            // 16384 floats per step
#define NCTA  128                  // persistent CTAs, all wave-1 resident
#define UNITS 4                    // hidden units per CTA
#define ROWS  16                   // gate rows per CTA (4 gates x 4 units)
#define NTHR  512                  // 16 warps
#define NSEG  16                   // k-segments per row (one per warp)
#define FLAG_TARGET (NCTA * 4)     // 4 release-REDs per CTA per step

// Dynamic SMEM layout (floats)
#define SMEM_W2   (HH * ROWS * 2)     // duplicated weight pairs: 64KB
#define SMEM_PART (ROWS * NSEG * BB)  // partials [r][seg][b]: 32KB
#define SMEM_FLOATS (SMEM_W2 + SMEM_PART + 64)
#define SMEM_BYTES  (SMEM_FLOATS * 4)

// Inter-step hidden state [t][j][b] (b fastest). Distinct buffer per step
// => one-way producer/consumer sync, no anti-dependency.
__device__ float    g_h[(size_t)TT * HB];   // ~268 MB static scratch
__device__ unsigned g_ctr[TT];              // per-step completion counters

__global__ void init_kernel() {
    int i = blockIdx.x * blockDim.x + threadIdx.x;
    if (i < TT) g_ctr[i] = 0u;
}

// Packed f32x2 FMA (Blackwell packed fp32 pipe).
__device__ __forceinline__ void fma2(unsigned long long& d,
                                     unsigned long long a,
                                     unsigned long long b) {
    asm("fma.rn.f32x2 %0, %1, %2, %0;" : "+l"(d) : "l"(a), "l"(b));
}

// Sigmoid via __expf is safe (R2 evidence: rel_err 2.9e-7). tanh MUST be
// accurate tanhf: the 1-2/(1+e^2x) trick cancels near 0 and its error
// accumulates in c over 4096 steps (R3: rel_err 7.1e-4, too close to 1e-3).
__device__ __forceinline__ float sig_f(float x) {
    return __fdividef(1.0f, 1.0f + __expf(-x));
}

__global__ void __launch_bounds__(NTHR, 1)
lstm_kernel(const float* __restrict__ x0,     // (T,B,1)
            const float* __restrict__ W_ih,   // (4H,1)
            const float* __restrict__ W_hh,   // (4H,H) row-major
            const float* __restrict__ b_ih,   // (4H)
            const float* __restrict__ b_hh)   // (4H)
{
    extern __shared__ float sm[];
    float* W2   = sm;                    // [k][r] duplicated pairs (w,w)
    float* part = sm + SMEM_W2;          // [r][seg][b]
    float* x0s  = part + SMEM_PART;      // 32
    float* wih  = x0s + 32;              // 16
    float* bsum = wih + 16;              // 16

    const int tid  = threadIdx.x;
    const int lane = tid & 31;
    const int w    = tid >> 5;           // warp 0..15 = k-segment
    const int kh   = lane >> 4;          // row-half: rows 8*kh .. 8*kh+7
    const int p    = lane & 15;          // batch pair -> batches 2p, 2p+1
    const int kbeg = w * 32;             // 32 k's per warp
    const int j0   = blockIdx.x * UNITS;

    // Stage W_hh slice, k-major, duplicated pairs: W2[(k*16+r)*2 + {0,1}] = w.
    for (int idx = tid; idx < ROWS * HH; idx += NTHR) {
        int r = idx & 15, k = idx >> 4;
        int grow = (r >> 2) * HH + j0 + (r & 3);   // gate*512 + j0 + unit
        float wv = W_hh[(size_t)grow * HH + k];
        W2[(k * ROWS + r) * 2 + 0] = wv;
        W2[(k * ROWS + r) * 2 + 1] = wv;
    }
    if (tid < ROWS) {
        int grow = (tid >> 2) * HH + j0 + (tid & 3);
        wih[tid]  = W_ih[grow];
        bsum[tid] = b_ih[grow] + b_hh[grow];
    }
    __syncthreads();

    // Epilogue threads (tid<128): warp u owns unit j0+u, lane b = batch.
    float c_reg = 0.0f;

    for (int t = 0; t < TT; ++t) {
        // Warp 15 lane 0 polls (overlaps own CTA's epilogue of step t-1).
        if (t && tid == NTHR - 32) {
            unsigned v;
            do {
                asm volatile("ld.acquire.gpu.global.u32 %0, [%1];"
                             : "=r"(v) : "l"(g_ctr + (t - 1)) : "memory");
            } while (v < (unsigned)FLAG_TARGET);
        }
        if ((tid >> 5) == 14) x0s[lane] = x0[t * BB + lane];  // warp 14 stages x0
        __syncthreads();

        // ---- gate dots: each warp does ALL 16 rows for its 32-k slice.
        // h[k][0..31] (128B) loaded ONCE per warp per k (both kh groups same
        // address -> broadcast); rows split by kh so W LDS stays 4x LDS.128.
        unsigned long long acc[8] = {0, 0, 0, 0, 0, 0, 0, 0};
        if (t) {
            const char*  hrow  = (const char*)(g_h + (size_t)(t - 1) * HB) + 8 * p;
            const float* wbase = W2 + kh * 16;   // rows 8*kh.. (64B offset)
            #pragma unroll 4
            for (int k = kbeg; k < kbeg + 32; ++k) {
                unsigned long long hp =
                    *(const unsigned long long*)(hrow + (size_t)k * 128); // LDG.64
                const float* wk = wbase + k * 32;
                ulonglong2 w01 = *(const ulonglong2*)(wk);       // rows +0,+1
                ulonglong2 w23 = *(const ulonglong2*)(wk + 4);   // rows +2,+3
                ulonglong2 w45 = *(const ulonglong2*)(wk + 8);   // rows +4,+5
                ulonglong2 w67 = *(const ulonglong2*)(wk + 12);  // rows +6,+7
                fma2(acc[0], w01.x, hp); fma2(acc[1], w01.y, hp);
                fma2(acc[2], w23.x, hp); fma2(acc[3], w23.y, hp);
                fma2(acc[4], w45.x, hp); fma2(acc[5], w45.y, hp);
                fma2(acc[6], w67.x, hp); fma2(acc[7], w67.y, hp);
            }
        }
        // partials[r][seg=w][b]
        #pragma unroll
        for (int j = 0; j < 8; ++j) {
            *(unsigned long long*)(part + ((8 * kh + j) * NSEG + w) * 32 + 2 * p)
                = acc[j];
        }
        __syncthreads();

        // ---- LSTM cell epilogue: 128 threads = 4 units x 32 batches ----
        if (tid < 128) {
            const int u = tid >> 5, b = tid & 31;
            const float xv = x0s[b];
            float gs[4];
            #pragma unroll
            for (int G = 0; G < 4; ++G) {
                const int r = G * 4 + u;
                const float* pr = part + r * (NSEG * 32) + b;
                float s = 0.0f;
                #pragma unroll
                for (int ss = 0; ss < NSEG; ++ss) s += pr[ss * 32];
                gs[G] = s + fmaf(wih[r], xv, bsum[r]);
            }
            float ig = sig_f(gs[0]);
            float fg = sig_f(gs[1]);
            float gg = tanhf(gs[2]);
            float og = sig_f(gs[3]);
            c_reg = fmaf(fg, c_reg, ig * gg);
            float hv = og * tanhf(c_reg);
            g_h[(size_t)t * HB + (j0 + u) * BB + b] = hv;

            // Per-warp release: warp's 32 STGs ordered by bar.warp.sync,
            // then one release-RED. No extra __syncthreads, no membar.
            __syncwarp();
            if (b == 0) {
                asm volatile("red.release.gpu.global.add.u32 [%0], 1;"
                             :: "l"(g_ctr + t) : "memory");
            }
        }
    }
}

// y[t][b] = x0 + b_lin + sum_j W_lin[j] * h[t][j][b]  — fully parallel over t,
// off the recurrence critical path. DRAM-bound: ~268MB read ≈ 35-40us.
__global__ void __launch_bounds__(256)
y_kernel(const float* __restrict__ x0,
         const float* __restrict__ W_lin,
         const float* __restrict__ b_lin,
         float* __restrict__ y)
{
    __shared__ float wl_s[HH];
    __shared__ float red[256];
    const int t = blockIdx.x, tid = threadIdx.x;
    for (int i = tid; i < HH; i += 256) wl_s[i] = W_lin[i];
    __syncthreads();
    const int b = tid & 31, jg = tid >> 5;
    const float* h = g_h + (size_t)t * HB;
    float acc = 0.0f;
    #pragma unroll 4
    for (int j = jg * 64; j < jg * 64 + 64; ++j)
        acc = fmaf(h[j * 32 + b], wl_s[j], acc);
    red[tid] = acc;
    __syncthreads();
    if (tid < 32) {
        float s = 0.0f;
        #pragma unroll
        for (int g = 0; g < 8; ++g) s += red[g * 32 + tid];
        y[t * BB + tid] = s + x0[t * BB + tid] + b_lin[0];
    }
}

extern "C" void kernel_launch(void* const* d_in, const int* in_sizes, int n_in,
                              void* d_out, int out_size)
{
    const float* x0    = (const float*)d_in[0];
    const float* W_ih  = (const float*)d_in[1];
    const float* W_hh  = (const float*)d_in[2];
    const float* b_ih  = (const float*)d_in[3];
    const float* b_hh  = (const float*)d_in[4];
    const float* W_lin = (const float*)d_in[5];
    const float* b_lin = (const float*)d_in[6];
    float* y = (float*)d_out;

    cudaFuncSetAttribute(lstm_kernel,
                         cudaFuncAttributeMaxDynamicSharedMemorySize, SMEM_BYTES);

    init_kernel<<<(TT + 255) / 256, 256>>>();
    lstm_kernel<<<NCTA, NTHR, SMEM_BYTES>>>(x0, W_ih, W_hh, b_ih, b_hh);
    y_kernel<<<TT, 256>>>(x0, W_lin, b_lin, y);
}

// round 5
// speedup vs baseline: 2.4516x; 1.1386x over previous
#include <cuda_runtime.h>
#include <math.h>

// Problem constants
#define TT    4096
#define BB    32
#define HH    512
#define HB    (HH * BB)            // 16384 floats per step
#define NCTA  128                  // persistent CTAs, all wave-1 resident
#define UNITS 4                    // hidden units per CTA
#define ROWS  16                   // gate rows per CTA (4 gates x 4 units)
#define NTHR  512                  // 16 warps
#define NSEG  16                   // k-segments per row (one per warp)
#define HALF_TGT 64u               // CTAs per half-barrier

// Dynamic SMEM layout (floats)
#define PART_FLOATS (ROWS * NSEG * BB)          // 8192 floats = 32KB per buffer
#define SMEM_W2     (HH * ROWS * 2)             // duplicated weights: 64KB
#define SMEM_FLOATS (SMEM_W2 + 2 * PART_FLOATS + 128)
#define SMEM_BYTES  (SMEM_FLOATS * 4)           // ~131.5KB

// Inter-step hidden state [t][j][b] (b fastest). Distinct buffer per step
// => one-way producer/consumer sync, no anti-dependency.
__device__ float    g_h[(size_t)TT * HB];   // ~268 MB static scratch
__device__ unsigned g_ctr[2];               // cumulative per-half counters

__global__ void init_kernel() { if (threadIdx.x < 2) g_ctr[threadIdx.x] = 0u; }

// Packed f32x2 FMA (Blackwell packed fp32 pipe).
__device__ __forceinline__ void fma2(unsigned long long& d,
                                     unsigned long long a,
                                     unsigned long long b) {
    asm("fma.rn.f32x2 %0, %1, %2, %0;" : "+l"(d) : "l"(a), "l"(b));
}

// Sigmoid via __expf is safe (R2/R4 evidence). tanh MUST stay accurate tanhf
// (R3: approx tanh -> rel_err 7e-4, too close to the 1e-3 gate).
__device__ __forceinline__ float sig_f(float x) {
    return __fdividef(1.0f, 1.0f + __expf(-x));
}

__global__ void __launch_bounds__(NTHR, 1)
lstm_kernel(const float* __restrict__ x0,     // (T,B,1)
            const float* __restrict__ W_ih,   // (4H,1)
            const float* __restrict__ W_hh,   // (4H,H) row-major
            const float* __restrict__ b_ih,   // (4H)
            const float* __restrict__ b_hh)   // (4H)
{
    extern __shared__ float sm[];
    float*    W2   = sm;                        // [k][r] duplicated pairs
    float*    part = sm + SMEM_W2;              // 2 x [r][seg][b]
    float*    x0s  = part + 2 * PART_FLOATS;    // 2 x 32 (double-buffered)
    float*    wih  = x0s + 64;                  // 16
    float*    bsum = wih + 16;                  // 16
    unsigned* smf  = (unsigned*)(bsum + 16);    // 2 relay words

    const int tid  = threadIdx.x;
    const int lane = tid & 31;
    const int w    = tid >> 5;           // warp 0..15 = k-segment
    const int kh   = lane >> 4;          // row-half: rows 8*kh .. 8*kh+7
    const int p    = lane & 15;          // batch pair -> batches 2p, 2p+1
    const int kbeg = w * 32;             // 32 k's per warp
    const int half = w >> 3;             // which producer-half this warp consumes
    const int j0   = blockIdx.x * UNITS;
    const unsigned myctr = (blockIdx.x < 64) ? 0u : 1u;   // half I produce into

    // Stage W_hh slice, k-major, duplicated pairs: W2[(k*16+r)*2 + {0,1}] = w.
    for (int idx = tid; idx < ROWS * HH; idx += NTHR) {
        int r = idx & 15, k = idx >> 4;
        int grow = (r >> 2) * HH + j0 + (r & 3);   // gate*512 + j0 + unit
        float wv = W_hh[(size_t)grow * HH + k];
        W2[(k * ROWS + r) * 2 + 0] = wv;
        W2[(k * ROWS + r) * 2 + 1] = wv;
    }
    if (tid < ROWS) {
        int grow = (tid >> 2) * HH + j0 + (tid & 3);
        wih[tid]  = W_ih[grow];
        bsum[tid] = b_ih[grow] + b_hh[grow];
    }
    if (tid < 2)  smf[tid] = 0u;
    if (w == 14)  x0s[lane] = x0[lane];          // x0 for t=0
    __syncthreads();

    const unsigned smf0 = (unsigned)__cvta_generic_to_shared(smf);
    float c_reg = 0.0f;     // epilogue threads (tid<128): unit w, batch lane
    float xnext = 0.0f;

    for (int t = 0; t < TT; ++t) {
        // Prefetch next step's x0 line BEFORE the wait (hides the DRAM miss).
        if (w == 14 && t + 1 < TT) xnext = x0[(t + 1) * BB + lane];

        // ---- half-barrier wait: poller warp -> smem relay -> consumers ----
        if (t) {
            const unsigned fa = smf0 + 4u * (unsigned)half;
            if ((w == 4 || w == 12) && lane == 0) {   // poller for own half
                unsigned v;
                do {
                    asm volatile("ld.acquire.gpu.global.u32 %0, [%1];"
                                 : "=r"(v) : "l"(g_ctr + half) : "memory");
                } while (v < HALF_TGT * (unsigned)t);
                asm volatile("st.release.cta.shared.u32 [%0], %1;"
                             :: "r"(fa), "r"((unsigned)t) : "memory");
            } else {
                unsigned s;
                do {
                    asm volatile("ld.acquire.cta.shared.u32 %0, [%1];"
                                 : "=r"(s) : "r"(fa) : "memory");
                } while (s < (unsigned)t);
            }
        }

        // ---- gate dots: all 16 rows per warp for its 32-k slice; h loads
        // software-pipelined in groups of 4 (MLP>=4, latency under FMAs). ----
        unsigned long long acc[8] = {0, 0, 0, 0, 0, 0, 0, 0};
        if (t) {
            const unsigned long long* hq =
                (const unsigned long long*)(g_h + (size_t)(t - 1) * HB) + p;
            const float* wbase = W2 + kh * 16;
            unsigned long long hA[4], hB[4];
            #pragma unroll
            for (int i = 0; i < 4; ++i) hA[i] = hq[(size_t)(kbeg + i) * 16];
            #pragma unroll
            for (int g = 0; g < 8; ++g) {
                unsigned long long* hc = (g & 1) ? hB : hA;
                unsigned long long* hn = (g & 1) ? hA : hB;
                if (g < 7) {
                    #pragma unroll
                    for (int i = 0; i < 4; ++i)
                        hn[i] = hq[(size_t)(kbeg + (g + 1) * 4 + i) * 16];
                }
                #pragma unroll
                for (int i = 0; i < 4; ++i) {
                    const float* wk = wbase + (kbeg + g * 4 + i) * 32;
                    ulonglong2 w01 = *(const ulonglong2*)(wk);
                    ulonglong2 w23 = *(const ulonglong2*)(wk + 4);
                    ulonglong2 w45 = *(const ulonglong2*)(wk + 8);
                    ulonglong2 w67 = *(const ulonglong2*)(wk + 12);
                    fma2(acc[0], w01.x, hc[i]); fma2(acc[1], w01.y, hc[i]);
                    fma2(acc[2], w23.x, hc[i]); fma2(acc[3], w23.y, hc[i]);
                    fma2(acc[4], w45.x, hc[i]); fma2(acc[5], w45.y, hc[i]);
                    fma2(acc[6], w67.x, hc[i]); fma2(acc[7], w67.y, hc[i]);
                }
            }
        }
        float* pb = part + (t & 1) * PART_FLOATS;   // double-buffered partials
        #pragma unroll
        for (int j = 0; j < 8; ++j)
            *(unsigned long long*)(pb + ((8 * kh + j) * NSEG + w) * 32 + 2 * p)
                = acc[j];
        __syncthreads();    // the ONLY CTA-wide barrier per step

        // Publish next x0 AFTER the barrier: epilogue(t-1) readers of this
        // buffer are provably done (flag chain), epilogue(t) uses the other.
        if (w == 14) x0s[((t + 1) & 1) * 32 + lane] = xnext;

        // ---- LSTM cell epilogue: 128 threads = 4 units x 32 batches ----
        if (tid < 128) {
            const int u = w, b = lane;
            const float xv = x0s[(t & 1) * 32 + b];
            float gs[4];
            #pragma unroll
            for (int G = 0; G < 4; ++G) {
                const int r = G * 4 + u;
                const float* pr = pb + r * (NSEG * 32) + b;
                float s = 0.0f;
                #pragma unroll
                for (int ss = 0; ss < NSEG; ++ss) s += pr[ss * 32];
                gs[G] = s + fmaf(wih[r], xv, bsum[r]);
            }
            float ig = sig_f(gs[0]);
            float fg = sig_f(gs[1]);
            float gg = tanhf(gs[2]);
            float og = sig_f(gs[3]);
            c_reg = fmaf(fg, c_reg, ig * gg);
            float hv = og * tanhf(c_reg);
            g_h[(size_t)t * HB + (j0 + u) * BB + b] = hv;

            // One release-RED per CTA: named bar among the 4 epilogue warps
            // orders all 128 STGs into the releasing thread's hb, then RED.
            asm volatile("bar.sync 1, 128;" ::: "memory");
            if (tid == 0)
                asm volatile("red.release.gpu.global.add.u32 [%0], 1;"
                             :: "l"(g_ctr + myctr) : "memory");
        }
    }
}

// y[t][b] = x0 + b_lin + sum_j W_lin[j] * h[t][j][b]  — fully parallel over t,
// off the recurrence critical path. DRAM-bound: ~268MB read ≈ 35-40us.
__global__ void __launch_bounds__(256)
y_kernel(const float* __restrict__ x0,
         const float* __restrict__ W_lin,
         const float* __restrict__ b_lin,
         float* __restrict__ y)
{
    __shared__ float wl_s[HH];
    __shared__ float red[256];
    const int t = blockIdx.x, tid = threadIdx.x;
    for (int i = tid; i < HH; i += 256) wl_s[i] = W_lin[i];
    __syncthreads();
    const int b = tid & 31, jg = tid >> 5;
    const float* h = g_h + (size_t)t * HB;
    float acc = 0.0f;
    #pragma unroll 4
    for (int j = jg * 64; j < jg * 64 + 64; ++j)
        acc = fmaf(h[j * 32 + b], wl_s[j], acc);
    red[tid] = acc;
    __syncthreads();
    if (tid < 32) {
        float s = 0.0f;
        #pragma unroll
        for (int g = 0; g < 8; ++g) s += red[g * 32 + tid];
        y[t * BB + tid] = s + x0[t * BB + tid] + b_lin[0];
    }
}

extern "C" void kernel_launch(void* const* d_in, const int* in_sizes, int n_in,
                              void* d_out, int out_size)
{
    const float* x0    = (const float*)d_in[0];
    const float* W_ih  = (const float*)d_in[1];
    const float* W_hh  = (const float*)d_in[2];
    const float* b_ih  = (const float*)d_in[3];
    const float* b_hh  = (const float*)d_in[4];
    const float* W_lin = (const float*)d_in[5];
    const float* b_lin = (const float*)d_in[6];
    float* y = (float*)d_out;

    cudaFuncSetAttribute(lstm_kernel,
                         cudaFuncAttributeMaxDynamicSharedMemorySize, SMEM_BYTES);

    init_kernel<<<1, 32>>>();
    lstm_kernel<<<NCTA, NTHR, SMEM_BYTES>>>(x0, W_ih, W_hh, b_ih, b_hh);
    y_kernel<<<TT, 256>>>(x0, W_lin, b_lin, y);
}

// round 8
// speedup vs baseline: 2.6763x; 1.0917x over previous
#include <cuda_runtime.h>
#include <math.h>

// Problem constants
#define TT    4096
#define BB    32
#define HH    512
#define HB    (HH * BB)            // 16384 floats per step
#define NCTA  128                  // persistent CTAs, all wave-1 resident
#define UNITS 4                    // hidden units per CTA
#define ROWS  16                   // gate rows per CTA (4 gates x 4 units)
#define NTHR  512                  // 16 warps
#define NSEG  16                   // k-segments per row (one per warp)
#define NGRP  16                   // barrier groups (8 CTAs each)
#define CTR_STRIDE 64              // 256B between counters -> distinct LTS lines

// Dynamic SMEM layout (floats)
#define PART_FLOATS (ROWS * NSEG * BB)          // 8192 floats = 32KB per buffer
#define SMEM_W2     (HH * ROWS * 2)             // duplicated weights: 64KB
#define SMEM_FLOATS (SMEM_W2 + 2 * PART_FLOATS + 128)
#define SMEM_BYTES  (SMEM_FLOATS * 4)           // ~131.5KB

// Inter-step hidden state [t][j][b] (b fastest). Distinct buffer per step
// => one-way producer/consumer sync, no anti-dependency.
__device__ float g_h[(size_t)TT * HB];   // ~268 MB static scratch
// 16 cumulative group counters (group g = CTAs 8g..8g+7), padded 256B apart.
// PROVEN primitives only: red.release.gpu.add publish + ld.acquire.gpu poll
// (the R6/R7 plain-store/cg-load flag scheme hung twice; never again).
__device__ __align__(256) unsigned g_ctr16[NGRP * CTR_STRIDE];

__global__ void init_kernel() { g_ctr16[threadIdx.x] = 0u; }  // 1024 threads

// Packed f32x2 FMA (Blackwell packed fp32 pipe).
__device__ __forceinline__ void fma2(unsigned long long& d,
                                     unsigned long long a,
                                     unsigned long long b) {
    asm("fma.rn.f32x2 %0, %1, %2, %0;" : "+l"(d) : "l"(a), "l"(b));
}

// Sigmoid via __expf is safe (R2/R4/R5 evidence). tanh MUST stay accurate
// tanhf (R3: approx tanh -> rel_err 7e-4, too close to the 1e-3 gate).
__device__ __forceinline__ float sig_f(float x) {
    return __fdividef(1.0f, 1.0f + __expf(-x));
}

__global__ void __launch_bounds__(NTHR, 1)
lstm_kernel(const float* __restrict__ x0,     // (T,B,1)
            const float* __restrict__ W_ih,   // (4H,1)
            const float* __restrict__ W_hh,   // (4H,H) row-major
            const float* __restrict__ b_ih,   // (4H)
            const float* __restrict__ b_hh)   // (4H)
{
    extern __shared__ float sm[];
    float* W2   = sm;                        // [k][r] duplicated pairs
    float* part = sm + SMEM_W2;              // 2 x [r][seg][b]
    float* x0s  = part + 2 * PART_FLOATS;    // 2 x 32 (double-buffered)
    float* wih  = x0s + 64;                  // 16
    float* bsum = wih + 16;                  // 16

    const int tid  = threadIdx.x;
    const int lane = tid & 31;
    const int w    = tid >> 5;           // warp 0..15 = k-segment
    const int kh   = lane >> 4;          // row-half: rows 8*kh .. 8*kh+7
    const int p    = lane & 15;          // batch pair -> batches 2p, 2p+1
    const int kbeg = w * 32;             // 32 k's per warp
    const int j0   = blockIdx.x * UNITS;
    // Counter this warp CONSUMES: group producing units [32w, 32w+32).
    const unsigned* cons_ctr = g_ctr16 + w * CTR_STRIDE;
    // Counter this CTA PRODUCES into: group blockIdx.x>>3.
    unsigned* prod_ctr = g_ctr16 + (blockIdx.x >> 3) * CTR_STRIDE;

    // Stage W_hh slice, k-major, duplicated pairs: W2[(k*16+r)*2 + {0,1}] = w.
    for (int idx = tid; idx < ROWS * HH; idx += NTHR) {
        int r = idx & 15, k = idx >> 4;
        int grow = (r >> 2) * HH + j0 + (r & 3);   // gate*512 + j0 + unit
        float wv = W_hh[(size_t)grow * HH + k];
        W2[(k * ROWS + r) * 2 + 0] = wv;
        W2[(k * ROWS + r) * 2 + 1] = wv;
    }
    if (tid < ROWS) {
        int grow = (tid >> 2) * HH + j0 + (tid & 3);
        wih[tid]  = W_ih[grow];
        bsum[tid] = b_ih[grow] + b_hh[grow];
    }
    if (w == 14) x0s[lane] = x0[lane];           // x0 for t=0
    __syncthreads();

    float c_reg = 0.0f;     // epilogue threads (tid<128): unit w, batch lane
    float xnext = 0.0f;

    for (int t = 0; t < TT; ++t) {
        // Prefetch next step's x0 line BEFORE the wait (hides the DRAM miss).
        if (w == 14 && t + 1 < TT) xnext = x0[(t + 1) * BB + lane];

        // ---- per-warp group wait: my 8 producer CTAs x 4 warps = 32 REDs
        // per step, cumulative. One coalesced acquire load per poll. ----
        if (t) {
            unsigned v;
            const unsigned tgt = 32u * (unsigned)t;
            do {
                asm volatile("ld.acquire.gpu.global.u32 %0, [%1];"
                             : "=r"(v) : "l"(cons_ctr) : "memory");
            } while (v < tgt);
        }

        // ---- gate dots: all 16 rows per warp for its 32-k slice; h loads
        // software-pipelined in groups of 4 (MLP>=4, latency under FMAs). ----
        unsigned long long acc[8] = {0, 0, 0, 0, 0, 0, 0, 0};
        if (t) {
            const unsigned long long* hq =
                (const unsigned long long*)(g_h + (size_t)(t - 1) * HB) + p;
            const float* wbase = W2 + kh * 16;
            unsigned long long hA[4], hB[4];
            #pragma unroll
            for (int i = 0; i < 4; ++i) hA[i] = hq[(size_t)(kbeg + i) * 16];
            #pragma unroll
            for (int g = 0; g < 8; ++g) {
                unsigned long long* hc = (g & 1) ? hB : hA;
                unsigned long long* hn = (g & 1) ? hA : hB;
                if (g < 7) {
                    #pragma unroll
                    for (int i = 0; i < 4; ++i)
                        hn[i] = hq[(size_t)(kbeg + (g + 1) * 4 + i) * 16];
                }
                #pragma unroll
                for (int i = 0; i < 4; ++i) {
                    const float* wk = wbase + (kbeg + g * 4 + i) * 32;
                    ulonglong2 w01 = *(const ulonglong2*)(wk);
                    ulonglong2 w23 = *(const ulonglong2*)(wk + 4);
                    ulonglong2 w45 = *(const ulonglong2*)(wk + 8);
                    ulonglong2 w67 = *(const ulonglong2*)(wk + 12);
                    fma2(acc[0], w01.x, hc[i]); fma2(acc[1], w01.y, hc[i]);
                    fma2(acc[2], w23.x, hc[i]); fma2(acc[3], w23.y, hc[i]);
                    fma2(acc[4], w45.x, hc[i]); fma2(acc[5], w45.y, hc[i]);
                    fma2(acc[6], w67.x, hc[i]); fma2(acc[7], w67.y, hc[i]);
                }
            }
        }
        float* pb = part + (t & 1) * PART_FLOATS;   // double-buffered partials
        #pragma unroll
        for (int j = 0; j < 8; ++j)
            *(unsigned long long*)(pb + ((8 * kh + j) * NSEG + w) * 32 + 2 * p)
                = acc[j];
        __syncthreads();    // the ONLY CTA-wide barrier per step

        // Publish next x0 AFTER the barrier: epilogue(t-1) readers of this
        // buffer are provably done (flag chain), epilogue(t) uses the other.
        if (w == 14) x0s[((t + 1) & 1) * 32 + lane] = xnext;

        // ---- LSTM cell epilogue: 128 threads = 4 units x 32 batches ----
        if (tid < 128) {
            const int u = w, b = lane;
            const float xv = x0s[(t & 1) * 32 + b];
            float gs[4];
            #pragma unroll
            for (int G = 0; G < 4; ++G) {
                const int r = G * 4 + u;
                const float* pr = pb + r * (NSEG * 32) + b;
                float s = 0.0f;
                #pragma unroll
                for (int ss = 0; ss < NSEG; ++ss) s += pr[ss * 32];
                gs[G] = s + fmaf(wih[r], xv, bsum[r]);
            }
            float ig = sig_f(gs[0]);
            float fg = sig_f(gs[1]);
            float gg = tanhf(gs[2]);
            float og = sig_f(gs[3]);
            c_reg = fmaf(fg, c_reg, ig * gg);
            float hv = og * tanhf(c_reg);
            g_h[(size_t)t * HB + (j0 + u) * BB + b] = hv;

            // Per-warp publish (earlier than a CTA-wide bar): this warp's 32
            // h-STGs are ordered into lane 0 by __syncwarp, then ONE
            // release-RED. 32 single-lane REDs per counter per step.
            __syncwarp();
            if (b == 0)
                asm volatile("red.release.gpu.global.add.u32 [%0], 1;"
                             :: "l"(prod_ctr) : "memory");
        }
    }
}

// y[t][b] = x0 + b_lin + sum_j W_lin[j] * h[t][j][b]  — fully parallel over t,
// off the recurrence critical path. DRAM-bound: ~268MB read ≈ 35-40us.
__global__ void __launch_bounds__(256)
y_kernel(const float* __restrict__ x0,
         const float* __restrict__ W_lin,
         const float* __restrict__ b_lin,
         float* __restrict__ y)
{
    __shared__ float wl_s[HH];
    __shared__ float red[256];
    const int t = blockIdx.x, tid = threadIdx.x;
    for (int i = tid; i < HH; i += 256) wl_s[i] = W_lin[i];
    __syncthreads();
    const int b = tid & 31, jg = tid >> 5;
    const float* h = g_h + (size_t)t * HB;
    float acc = 0.0f;
    #pragma unroll 4
    for (int j = jg * 64; j < jg * 64 + 64; ++j)
        acc = fmaf(h[j * 32 + b], wl_s[j], acc);
    red[tid] = acc;
    __syncthreads();
    if (tid < 32) {
        float s = 0.0f;
        #pragma unroll
        for (int g = 0; g < 8; ++g) s += red[g * 32 + tid];
        y[t * BB + tid] = s + x0[t * BB + tid] + b_lin[0];
    }
}

extern "C" void kernel_launch(void* const* d_in, const int* in_sizes, int n_in,
                              void* d_out, int out_size)
{
    const float* x0    = (const float*)d_in[0];
    const float* W_ih  = (const float*)d_in[1];
    const float* W_hh  = (const float*)d_in[2];
    const float* b_ih  = (const float*)d_in[3];
    const float* b_hh  = (const float*)d_in[4];
    const float* W_lin = (const float*)d_in[5];
    const float* b_lin = (const float*)d_in[6];
    float* y = (float*)d_out;

    cudaFuncSetAttribute(lstm_kernel,
                         cudaFuncAttributeMaxDynamicSharedMemorySize, SMEM_BYTES);

    init_kernel<<<1, NGRP * CTR_STRIDE>>>();
    lstm_kernel<<<NCTA, NTHR, SMEM_BYTES>>>(x0, W_ih, W_hh, b_ih, b_hh);
    y_kernel<<<TT, 256>>>(x0, W_lin, b_lin, y);
}